// round 2
// baseline (speedup 1.0000x reference)
#include <cuda_runtime.h>

#define HID   768
#define HID3  2304
#define SEQ   2048
#define BATCH 8
#define TOK   (BATCH * SEQ)

// Scratch (allocation-free rule: __device__ globals)
__device__ float g_qkv[(size_t)TOK * HID3];        // 151 MB: [token, 3H] (q|k|v)
__device__ float g_S[(size_t)BATCH * SEQ * SEQ];   // 134 MB: attention logits / probs

// ---------------------------------------------------------------------------
// 128x128x16 fp32 tile GEMM body. NT_B=true: C=A*B^T (both K-major rows).
// NT_B=false: C=A*B (B row-major [K,N]).
// ---------------------------------------------------------------------------
template <bool NT_B, bool BIAS>
__device__ __forceinline__ void gemm_tile_128(
    const float* __restrict__ A, int lda,
    const float* __restrict__ B, int ldb,
    const float* __restrict__ bias,
    float* __restrict__ C, int ldc, int K)
{
    __shared__ float As[16][128];
    __shared__ float Bs[16][128];

    const int tid  = threadIdx.x;
    const int tx   = tid & 15;
    const int ty   = tid >> 4;
    const int row0 = blockIdx.y * 128;
    const int col0 = blockIdx.x * 128;

    float acc[8][8];
#pragma unroll
    for (int i = 0; i < 8; i++)
#pragma unroll
        for (int j = 0; j < 8; j++) acc[i][j] = 0.f;

    for (int k0 = 0; k0 < K; k0 += 16) {
        // ---- load tiles (each thread: 2 float4 of A, 2 of B) ----
#pragma unroll
        for (int s = 0; s < 2; s++) {
            int q  = tid + s * 256;
            int r  = q >> 2;           // 0..127 (M / N row for NT)
            int kc = (q & 3) << 2;     // 0,4,8,12
            float4 va = *(const float4*)(A + (size_t)(row0 + r) * lda + (k0 + kc));
            As[kc + 0][r] = va.x; As[kc + 1][r] = va.y;
            As[kc + 2][r] = va.z; As[kc + 3][r] = va.w;
            if (NT_B) {
                float4 vb = *(const float4*)(B + (size_t)(col0 + r) * ldb + (k0 + kc));
                Bs[kc + 0][r] = vb.x; Bs[kc + 1][r] = vb.y;
                Bs[kc + 2][r] = vb.z; Bs[kc + 3][r] = vb.w;
            } else {
                int kr = q >> 5;           // 0..15
                int nc = (q & 31) << 2;    // 0..124
                float4 vb = *(const float4*)(B + (size_t)(k0 + kr) * ldb + (col0 + nc));
                *(float4*)&Bs[kr][nc] = vb;
            }
        }
        __syncthreads();

        // ---- compute ----
#pragma unroll
        for (int kk = 0; kk < 16; kk++) {
            float a[8], b8[8];
            *(float4*)(a)      = *(const float4*)&As[kk][ty * 8];
            *(float4*)(a + 4)  = *(const float4*)&As[kk][ty * 8 + 4];
            *(float4*)(b8)     = *(const float4*)&Bs[kk][tx * 8];
            *(float4*)(b8 + 4) = *(const float4*)&Bs[kk][tx * 8 + 4];
#pragma unroll
            for (int i = 0; i < 8; i++)
#pragma unroll
                for (int j = 0; j < 8; j++)
                    acc[i][j] = fmaf(a[i], b8[j], acc[i][j]);
        }
        __syncthreads();
    }

    // ---- epilogue ----
#pragma unroll
    for (int i = 0; i < 8; i++) {
        int r = row0 + ty * 8 + i;
#pragma unroll
        for (int j = 0; j < 8; j += 4) {
            int c = col0 + tx * 8 + j;
            float4 v;
            v.x = acc[i][j + 0]; v.y = acc[i][j + 1];
            v.z = acc[i][j + 2]; v.w = acc[i][j + 3];
            if (BIAS) {
                v.x += bias[c + 0]; v.y += bias[c + 1];
                v.z += bias[c + 2]; v.w += bias[c + 3];
            }
            *(float4*)(C + (size_t)r * ldc + c) = v;
        }
    }
}

// ---- stage 1: QKV = x @ W^T + b    [16384, 2304] ----
__global__ __launch_bounds__(256) void qkv_kernel(
    const float* __restrict__ x, const float* __restrict__ W,
    const float* __restrict__ b)
{
    gemm_tile_128<true, true>(x, HID, W, HID, b, g_qkv, HID3, HID);
}

// ---- stage 2: S = q @ k^T per batch   [2048, 2048] x 8 ----
__global__ __launch_bounds__(256) void qk_kernel()
{
    const float* base = g_qkv + (size_t)blockIdx.z * SEQ * HID3;
    gemm_tile_128<true, false ? true : false>(  // NT
        base, HID3, base + HID, HID3, nullptr,
        g_S + (size_t)blockIdx.z * SEQ * SEQ, SEQ, HID);
}

// ---- stage 3: row softmax over S (16384 rows x 2048), in place ----
__global__ __launch_bounds__(256) void softmax_kernel()
{
    float4* p4 = (float4*)(g_S + (size_t)blockIdx.x * SEQ);
    const int tid = threadIdx.x;
    float4 v0 = p4[tid];
    float4 v1 = p4[tid + 256];

    float m = fmaxf(fmaxf(fmaxf(v0.x, v0.y), fmaxf(v0.z, v0.w)),
                    fmaxf(fmaxf(v1.x, v1.y), fmaxf(v1.z, v1.w)));
    __shared__ float red[8];
    __shared__ float red2[8];
#pragma unroll
    for (int o = 16; o; o >>= 1)
        m = fmaxf(m, __shfl_xor_sync(0xffffffffu, m, o));
    if ((tid & 31) == 0) red[tid >> 5] = m;
    __syncthreads();
    float bm = red[0];
#pragma unroll
    for (int i = 1; i < 8; i++) bm = fmaxf(bm, red[i]);

    v0.x = __expf(v0.x - bm); v0.y = __expf(v0.y - bm);
    v0.z = __expf(v0.z - bm); v0.w = __expf(v0.w - bm);
    v1.x = __expf(v1.x - bm); v1.y = __expf(v1.y - bm);
    v1.z = __expf(v1.z - bm); v1.w = __expf(v1.w - bm);

    float s = ((v0.x + v0.y) + (v0.z + v0.w)) + ((v1.x + v1.y) + (v1.z + v1.w));
#pragma unroll
    for (int o = 16; o; o >>= 1)
        s += __shfl_xor_sync(0xffffffffu, s, o);
    if ((tid & 31) == 0) red2[tid >> 5] = s;
    __syncthreads();
    float ts = red2[0];
#pragma unroll
    for (int i = 1; i < 8; i++) ts += red2[i];
    float inv = 1.0f / ts;

    v0.x *= inv; v0.y *= inv; v0.z *= inv; v0.w *= inv;
    v1.x *= inv; v1.y *= inv; v1.z *= inv; v1.w *= inv;
    p4[tid] = v0;
    p4[tid + 256] = v1;
}

// ---- stage 4: out = P @ v per batch   [2048, 768] x 8 ----
__global__ __launch_bounds__(256) void pv_kernel(float* __restrict__ out)
{
    const float* P = g_S + (size_t)blockIdx.z * SEQ * SEQ;
    const float* V = g_qkv + (size_t)blockIdx.z * SEQ * HID3 + 2 * HID;
    gemm_tile_128<false, false>(P, SEQ, V, HID3, nullptr,
                                out + (size_t)blockIdx.z * SEQ * HID, HID, SEQ);
}

extern "C" void kernel_launch(void* const* d_in, const int* in_sizes, int n_in,
                              void* d_out, int out_size)
{
    const float* x = (const float*)d_in[0];
    const float* W = (const float*)d_in[1];
    const float* b = (const float*)d_in[2];
    float* out = (float*)d_out;

    (void)in_sizes; (void)n_in; (void)out_size;

    qkv_kernel<<<dim3(HID3 / 128, TOK / 128, 1), 256>>>(x, W, b);
    qk_kernel<<<dim3(SEQ / 128, SEQ / 128, BATCH), 256>>>();
    softmax_kernel<<<dim3(TOK, 1, 1), 256>>>();
    pv_kernel<<<dim3(HID / 128, SEQ / 128, BATCH), 256>>>(out);
}

// round 9
// speedup vs baseline: 2.9268x; 2.9268x over previous
#include <cuda_runtime.h>
#include <cuda_bf16.h>
#include <cstdint>

#define HID   768
#define HID3  2304
#define SEQ   2048
#define BATCH 8
#define TOK   (BATCH * SEQ)

#define BM 128
#define BN 128
#define BK 64                 // bf16 elems per chunk = 128 B/row (SW128-friendly)
#define NSTAGE 3
#define STAGE_BYTES 32768     // A 16KB + B 16KB
#define SM_TOTAL (NSTAGE * STAGE_BYTES)   // 96 KB

// ---------------- scratch (__device__ globals, allocation-free rule) ----------------
__device__ __align__(1024) __nv_bfloat16 g_x_hi[(size_t)TOK * HID];
__device__ __align__(1024) __nv_bfloat16 g_x_lo[(size_t)TOK * HID];
__device__ __align__(1024) __nv_bfloat16 g_w_hi[(size_t)HID3 * HID];
__device__ __align__(1024) __nv_bfloat16 g_w_lo[(size_t)HID3 * HID];
__device__ __align__(1024) __nv_bfloat16 g_q_hi[(size_t)TOK * HID];
__device__ __align__(1024) __nv_bfloat16 g_q_lo[(size_t)TOK * HID];
__device__ __align__(1024) __nv_bfloat16 g_k_hi[(size_t)TOK * HID];
__device__ __align__(1024) __nv_bfloat16 g_k_lo[(size_t)TOK * HID];
__device__ __align__(1024) __nv_bfloat16 g_vT_hi[(size_t)BATCH * HID * SEQ]; // [b][dim][tok]
__device__ __align__(1024) __nv_bfloat16 g_vT_lo[(size_t)BATCH * HID * SEQ];
__device__ __align__(1024) float         g_S[(size_t)BATCH * SEQ * SEQ];
__device__ __align__(1024) __nv_bfloat16 g_P_hi[(size_t)TOK * SEQ];
__device__ __align__(1024) __nv_bfloat16 g_P_lo[(size_t)TOK * SEQ];

// ---------------- PTX helpers (sm_80-era only: legal on plain sm_103) ----------------
__device__ __forceinline__ uint32_t smem_u32(const void* p) {
    uint32_t a;
    asm("{ .reg .u64 t; cvta.to.shared.u64 t, %1; cvt.u32.u64 %0, t; }" : "=r"(a) : "l"(p));
    return a;
}
__device__ __forceinline__ void cp16(uint32_t dst, const void* src) {
    asm volatile("cp.async.cg.shared.global [%0], [%1], 16;"
                 :: "r"(dst), "l"(__cvta_generic_to_global(src)) : "memory");
}
#define CP_COMMIT() asm volatile("cp.async.commit_group;" ::: "memory")
#define CP_WAIT1()  asm volatile("cp.async.wait_group 1;" ::: "memory")

__device__ __forceinline__ void ldsm_x4(uint32_t& d0, uint32_t& d1, uint32_t& d2,
                                        uint32_t& d3, uint32_t addr) {
    asm volatile("ldmatrix.sync.aligned.m8n8.x4.shared.b16 {%0,%1,%2,%3}, [%4];"
                 : "=r"(d0), "=r"(d1), "=r"(d2), "=r"(d3) : "r"(addr));
}
__device__ __forceinline__ void mma16816(float (&c)[4], uint32_t a0, uint32_t a1,
                                         uint32_t a2, uint32_t a3,
                                         uint32_t b0, uint32_t b1) {
    asm volatile("mma.sync.aligned.m16n8k16.row.col.f32.bf16.bf16.f32 "
                 "{%0,%1,%2,%3}, {%4,%5,%6,%7}, {%8,%9}, {%0,%1,%2,%3};"
                 : "+f"(c[0]), "+f"(c[1]), "+f"(c[2]), "+f"(c[3])
                 : "r"(a0), "r"(a1), "r"(a2), "r"(a3), "r"(b0), "r"(b1));
}

__device__ __forceinline__ void split1(float v, __nv_bfloat16& h, __nv_bfloat16& l) {
    h = __float2bfloat16(v);
    l = __float2bfloat16(v - __bfloat162float(h));
}

// ---------------------------------------------------------------------------
// bf16x3 HMMA mainloop. C(128x128 fp32 regs) ~= (Ahi+Alo)(Bhi+Blo)^T via
// hi*hi + lo*hi + hi*lo. A,B K-major rows. 3-stage cp.async pipeline,
// SW128-swizzled smem, conflict-free ldmatrix. 8 warps: warp tile 32x64.
// acc[mt][nt][4]: mt in {0,1} (16-row tiles), nt in {0..7} (8-col tiles).
// ---------------------------------------------------------------------------
__device__ __forceinline__ void run_mainloop(
    const __nv_bfloat16* __restrict__ Ahi, const __nv_bfloat16* __restrict__ Alo, int lda,
    const __nv_bfloat16* __restrict__ Bhi, const __nv_bfloat16* __restrict__ Blo, int ldb,
    int K, int row0, int col0, char* smem, float (&acc)[2][8][4])
{
    const int tid  = threadIdx.x;
    const int lane = tid & 31, wid = tid >> 5;
    const int warp_m = wid >> 1, warp_n = wid & 1;
    const uint32_t sb = smem_u32(smem);

#pragma unroll
    for (int mt = 0; mt < 2; mt++)
#pragma unroll
        for (int nt = 0; nt < 8; nt++)
#pragma unroll
            for (int j = 0; j < 4; j++) acc[mt][nt][j] = 0.f;

    const int NIT = 3 * (K / BK);

    auto issue = [&](int it) {
        const int chunk = it / 3, combo = it - 3 * chunk;
        const __nv_bfloat16* A = (combo == 1) ? Alo : Ahi;
        const __nv_bfloat16* B = (combo == 2) ? Blo : Bhi;
        const int k0 = chunk * BK;
        const uint32_t st = sb + (uint32_t)(it % NSTAGE) * STAGE_BYTES;
#pragma unroll
        for (int w = 0; w < 4; w++) {
            int idx = tid + w * 256, r = idx >> 3, c8 = idx & 7;
            cp16(st + r * 128 + ((c8 ^ (r & 7)) << 4),
                 A + (size_t)(row0 + r) * lda + k0 + c8 * 8);
        }
#pragma unroll
        for (int w = 0; w < 4; w++) {
            int idx = tid + w * 256, r = idx >> 3, c8 = idx & 7;
            cp16(st + 16384 + r * 128 + ((c8 ^ (r & 7)) << 4),
                 B + (size_t)(col0 + r) * ldb + k0 + c8 * 8);
        }
    };

    issue(0); CP_COMMIT();
    issue(1); CP_COMMIT();

    // per-thread ldmatrix address invariants
    const int rowA = warp_m * 32 + (lane & 15);     // + mt*16
    const int hA   = lane >> 4, sA7 = rowA & 7;     // (mt*16 keeps r&7)
    const int rB   = warp_n * 64 + (lane & 7) + ((lane >> 4) << 3);  // + p*16
    const int hB   = (lane >> 3) & 1, sB7 = lane & 7;

    for (int it = 0; it < NIT; it++) {
        CP_WAIT1();
        __syncthreads();
        if (it + 2 < NIT) issue(it + 2);
        CP_COMMIT();

        const uint32_t sA = sb + (uint32_t)(it % NSTAGE) * STAGE_BYTES;
        const uint32_t sBs = sA + 16384;
#pragma unroll
        for (int k16 = 0; k16 < 4; k16++) {
            uint32_t a[2][4], b[4][4];
#pragma unroll
            for (int mt = 0; mt < 2; mt++)
                ldsm_x4(a[mt][0], a[mt][1], a[mt][2], a[mt][3],
                        sA + (rowA + mt * 16) * 128 + (((k16 * 2 + hA) ^ sA7) << 4));
#pragma unroll
            for (int p = 0; p < 4; p++)
                ldsm_x4(b[p][0], b[p][1], b[p][2], b[p][3],
                        sBs + (rB + p * 16) * 128 + (((k16 * 2 + hB) ^ sB7) << 4));
#pragma unroll
            for (int mt = 0; mt < 2; mt++)
#pragma unroll
                for (int nt = 0; nt < 8; nt++)
                    mma16816(acc[mt][nt], a[mt][0], a[mt][1], a[mt][2], a[mt][3],
                             b[nt >> 1][(nt & 1) * 2], b[nt >> 1][(nt & 1) * 2 + 1]);
        }
    }
}

// ---------------- stage 0: fp32 -> bf16 hi/lo split ----------------
__global__ __launch_bounds__(256) void split_kernel(
    const float* __restrict__ src, __nv_bfloat16* __restrict__ hi,
    __nv_bfloat16* __restrict__ lo, int n4)
{
    int i = blockIdx.x * 256 + threadIdx.x;
    if (i >= n4) return;
    float4 v = ((const float4*)src)[i];
    __nv_bfloat16 h0, l0, h1, l1, h2, l2, h3, l3;
    split1(v.x, h0, l0); split1(v.y, h1, l1);
    split1(v.z, h2, l2); split1(v.w, h3, l3);
    __nv_bfloat162* H = (__nv_bfloat162*)hi;
    __nv_bfloat162* L = (__nv_bfloat162*)lo;
    H[2 * i]     = __nv_bfloat162(h0, h1);
    H[2 * i + 1] = __nv_bfloat162(h2, h3);
    L[2 * i]     = __nv_bfloat162(l0, l1);
    L[2 * i + 1] = __nv_bfloat162(l2, l3);
}

// ---------------- stage 1: QKV = x @ W^T + b ; epilogue splits q,k and v^T ----------------
__global__ __launch_bounds__(256) void qkv_gemm(const float* __restrict__ bias)
{
    extern __shared__ char smem[];
    const int row0 = blockIdx.y * BM;
    const int col0 = blockIdx.x * BN;
    float acc[2][8][4];
    run_mainloop(g_x_hi, g_x_lo, HID, g_w_hi, g_w_lo, HID, HID, row0, col0, smem, acc);

    const int lane = threadIdx.x & 31, wid = threadIdx.x >> 5;
    const int warp_m = wid >> 1, warp_n = wid & 1;
    const int quad = lane >> 2, qt = lane & 3;
#pragma unroll
    for (int mt = 0; mt < 2; mt++)
#pragma unroll
        for (int h = 0; h < 2; h++) {
            const int t = row0 + warp_m * 32 + mt * 16 + quad + h * 8;
            const int bz = t >> 11, tr = t & 2047;
#pragma unroll
            for (int nt = 0; nt < 8; nt++) {
                const int gcol = col0 + warp_n * 64 + nt * 8 + qt * 2;
                float v0 = acc[mt][nt][2 * h]     + __ldg(bias + gcol);
                float v1 = acc[mt][nt][2 * h + 1] + __ldg(bias + gcol + 1);
                __nv_bfloat16 h0, l0, h1, l1;
                split1(v0, h0, l0); split1(v1, h1, l1);
                if (gcol < HID) {
                    size_t o = (size_t)t * HID + gcol;
                    *(__nv_bfloat162*)(g_q_hi + o) = __nv_bfloat162(h0, h1);
                    *(__nv_bfloat162*)(g_q_lo + o) = __nv_bfloat162(l0, l1);
                } else if (gcol < 2 * HID) {
                    size_t o = (size_t)t * HID + (gcol - HID);
                    *(__nv_bfloat162*)(g_k_hi + o) = __nv_bfloat162(h0, h1);
                    *(__nv_bfloat162*)(g_k_lo + o) = __nv_bfloat162(l0, l1);
                } else {
                    const int d = gcol - 2 * HID;
                    size_t o = ((size_t)bz * HID + d) * SEQ + tr;
                    g_vT_hi[o] = h0; g_vT_lo[o] = l0;
                    g_vT_hi[o + SEQ] = h1; g_vT_lo[o + SEQ] = l1;
                }
            }
        }
}

// ---------------- stage 2: S = q @ k^T (per batch) ----------------
__global__ __launch_bounds__(256) void qk_gemm()
{
    extern __shared__ char smem[];
    const int bz = blockIdx.z;
    const size_t off = (size_t)bz * SEQ * HID;
    const int row0 = blockIdx.y * BM;
    const int col0 = blockIdx.x * BN;
    float acc[2][8][4];
    run_mainloop(g_q_hi + off, g_q_lo + off, HID, g_k_hi + off, g_k_lo + off, HID,
                 HID, row0, col0, smem, acc);

    const int lane = threadIdx.x & 31, wid = threadIdx.x >> 5;
    const int warp_m = wid >> 1, warp_n = wid & 1;
    const int quad = lane >> 2, qt = lane & 3;
#pragma unroll
    for (int mt = 0; mt < 2; mt++)
#pragma unroll
        for (int h = 0; h < 2; h++) {
            const int m = row0 + warp_m * 32 + mt * 16 + quad + h * 8;
            float* Srow = g_S + ((size_t)bz * SEQ + m) * SEQ;
#pragma unroll
            for (int nt = 0; nt < 8; nt++) {
                const int c = col0 + warp_n * 64 + nt * 8 + qt * 2;
                float2 v; v.x = acc[mt][nt][2 * h]; v.y = acc[mt][nt][2 * h + 1];
                *(float2*)(Srow + c) = v;
            }
        }
}

// ---------------- stage 3: softmax + split P ----------------
__global__ __launch_bounds__(256) void softmax_split_kernel()
{
    const size_t row = blockIdx.x;
    const float4* p4 = (const float4*)(g_S + row * SEQ);
    const int tid = threadIdx.x;
    float4 v0 = p4[tid];
    float4 v1 = p4[tid + 256];

    float m = fmaxf(fmaxf(fmaxf(v0.x, v0.y), fmaxf(v0.z, v0.w)),
                    fmaxf(fmaxf(v1.x, v1.y), fmaxf(v1.z, v1.w)));
    __shared__ float red[8], red2[8];
#pragma unroll
    for (int o = 16; o; o >>= 1) m = fmaxf(m, __shfl_xor_sync(0xffffffffu, m, o));
    if ((tid & 31) == 0) red[tid >> 5] = m;
    __syncthreads();
    float bm = red[0];
#pragma unroll
    for (int i = 1; i < 8; i++) bm = fmaxf(bm, red[i]);

    v0.x = __expf(v0.x - bm); v0.y = __expf(v0.y - bm);
    v0.z = __expf(v0.z - bm); v0.w = __expf(v0.w - bm);
    v1.x = __expf(v1.x - bm); v1.y = __expf(v1.y - bm);
    v1.z = __expf(v1.z - bm); v1.w = __expf(v1.w - bm);

    float s = ((v0.x + v0.y) + (v0.z + v0.w)) + ((v1.x + v1.y) + (v1.z + v1.w));
#pragma unroll
    for (int o = 16; o; o >>= 1) s += __shfl_xor_sync(0xffffffffu, s, o);
    if ((tid & 31) == 0) red2[tid >> 5] = s;
    __syncthreads();
    float ts = red2[0];
#pragma unroll
    for (int i = 1; i < 8; i++) ts += red2[i];
    const float inv = 1.0f / ts;

    __nv_bfloat162* PH = (__nv_bfloat162*)(g_P_hi + row * SEQ);
    __nv_bfloat162* PL = (__nv_bfloat162*)(g_P_lo + row * SEQ);
    __nv_bfloat16 h0, l0, h1, l1;
    split1(v0.x * inv, h0, l0); split1(v0.y * inv, h1, l1);
    PH[2 * tid] = __nv_bfloat162(h0, h1); PL[2 * tid] = __nv_bfloat162(l0, l1);
    split1(v0.z * inv, h0, l0); split1(v0.w * inv, h1, l1);
    PH[2 * tid + 1] = __nv_bfloat162(h0, h1); PL[2 * tid + 1] = __nv_bfloat162(l0, l1);
    split1(v1.x * inv, h0, l0); split1(v1.y * inv, h1, l1);
    PH[2 * (tid + 256)] = __nv_bfloat162(h0, h1); PL[2 * (tid + 256)] = __nv_bfloat162(l0, l1);
    split1(v1.z * inv, h0, l0); split1(v1.w * inv, h1, l1);
    PH[2 * (tid + 256) + 1] = __nv_bfloat162(h0, h1); PL[2 * (tid + 256) + 1] = __nv_bfloat162(l0, l1);
}

// ---------------- stage 4: out = P @ v (per batch; B = vT, K-major) ----------------
__global__ __launch_bounds__(256) void pv_gemm(float* __restrict__ out)
{
    extern __shared__ char smem[];
    const int bz = blockIdx.z;
    const size_t pOff = (size_t)bz * SEQ * SEQ;
    const size_t vOff = (size_t)bz * HID * SEQ;
    const int row0 = blockIdx.y * BM;
    const int col0 = blockIdx.x * BN;
    float acc[2][8][4];
    run_mainloop(g_P_hi + pOff, g_P_lo + pOff, SEQ, g_vT_hi + vOff, g_vT_lo + vOff, SEQ,
                 SEQ, row0, col0, smem, acc);

    const int lane = threadIdx.x & 31, wid = threadIdx.x >> 5;
    const int warp_m = wid >> 1, warp_n = wid & 1;
    const int quad = lane >> 2, qt = lane & 3;
#pragma unroll
    for (int mt = 0; mt < 2; mt++)
#pragma unroll
        for (int h = 0; h < 2; h++) {
            const int m = row0 + warp_m * 32 + mt * 16 + quad + h * 8;
            float* Orow = out + ((size_t)bz * SEQ + m) * HID;
#pragma unroll
            for (int nt = 0; nt < 8; nt++) {
                const int c = col0 + warp_n * 64 + nt * 8 + qt * 2;
                float2 v; v.x = acc[mt][nt][2 * h]; v.y = acc[mt][nt][2 * h + 1];
                *(float2*)(Orow + c) = v;
            }
        }
}

// ---------------------------------------------------------------------------
extern "C" void kernel_launch(void* const* d_in, const int* in_sizes, int n_in,
                              void* d_out, int out_size)
{
    const float* x = (const float*)d_in[0];
    const float* W = (const float*)d_in[1];
    const float* b = (const float*)d_in[2];
    float* out = (float*)d_out;
    (void)in_sizes; (void)n_in; (void)out_size;

    cudaFuncSetAttribute(qkv_gemm, cudaFuncAttributeMaxDynamicSharedMemorySize, SM_TOTAL);
    cudaFuncSetAttribute(qk_gemm,  cudaFuncAttributeMaxDynamicSharedMemorySize, SM_TOTAL);
    cudaFuncSetAttribute(pv_gemm,  cudaFuncAttributeMaxDynamicSharedMemorySize, SM_TOTAL);

    __nv_bfloat16 *xh, *xl, *wh, *wl;
    cudaGetSymbolAddress((void**)&xh, g_x_hi); cudaGetSymbolAddress((void**)&xl, g_x_lo);
    cudaGetSymbolAddress((void**)&wh, g_w_hi); cudaGetSymbolAddress((void**)&wl, g_w_lo);

    int nx4 = TOK * HID / 4, nw4 = HID3 * HID / 4;
    split_kernel<<<(nx4 + 255) / 256, 256>>>(x, xh, xl, nx4);
    split_kernel<<<(nw4 + 255) / 256, 256>>>(W, wh, wl, nw4);

    qkv_gemm<<<dim3(HID3 / BN, TOK / BM, 1), 256, SM_TOTAL>>>(b);
    qk_gemm<<<dim3(SEQ / BN, SEQ / BM, BATCH), 256, SM_TOTAL>>>();
    softmax_split_kernel<<<TOK, 256>>>();
    pv_gemm<<<dim3(HID / BN, SEQ / BM, BATCH), 256, SM_TOTAL>>>(out);
}